// round 15
// baseline (speedup 1.0000x reference)
#include <cuda_runtime.h>
#include <cuda_bf16.h>

// BERT embedding fused gather — round 14 (round-10/11 design, resubmitted
// after two infra-level container failures; minor codegen simplifications).
// out[t,:] = token_table[seq[t]] + mean_{g<cnt} genre_table[gids[seq[t],g]] + pos_table[t % L]
//
// Design: occupancy-first with full up-front prefetch.
//  - BPW=2 tokens per warp (same l, adjacent batch rows)
//  - all ~9 long-latency loads per warp issued as one independent batch
//  - live state ~40 regs; __launch_bounds__(256,5) -> 40 warps/SM theoretical
//  - 25600 warps total for latency hiding + small tail
//  - pos row loaded once per warp, reused 2x; 512B coalesced stores
// No smem, no __syncthreads.

#define EV    32   // 128 floats = 32 float4
#define MAX_G 8
#define BPW   2    // batch rows (tokens) per warp, same l

__global__ __launch_bounds__(256, 5) void bert_embed_kernel(
    const int*    __restrict__ seq,          // [B*L]
    const float4* __restrict__ tok_table,    // [VOCAB][32]
    const float4* __restrict__ genre_table,  // [NG][32]
    const float4* __restrict__ pos_table,    // [MAX_LEN][32]
    const int4*   __restrict__ token_gids,   // [VOCAB][2]
    const int*    __restrict__ genre_counts, // [VOCAB]
    float4*       __restrict__ out,          // [B*L][32]
    int L, int B)
{
    const int lane = threadIdx.x & 31;
    const int w    = blockIdx.x * (blockDim.x >> 5) + (threadIdx.x >> 5);
    const int l    = w % L;
    const int b0   = (w / L) * BPW;
    if (b0 >= B) return;

    // Common case: full group (B % BPW == 0 here, so always true).
    const bool full = (b0 + BPW <= B);

    // ---- phase 1: issue every independent long-latency load ----
    const float4 pv = __ldg(&pos_table[l * EV + lane]);

    int tk[BPW];
    #pragma unroll
    for (int k = 0; k < BPW; k++)
        tk[k] = (full || b0 + k < B) ? __ldg(&seq[(b0 + k) * L + l]) : 0;

    int4   ga[BPW], gb[BPW];
    int    cnt[BPW];
    float4 tv[BPW];
    #pragma unroll
    for (int k = 0; k < BPW; k++) {
        ga[k]  = __ldg(&token_gids[tk[k] * 2 + 0]);
        gb[k]  = __ldg(&token_gids[tk[k] * 2 + 1]);
        cnt[k] = __ldg(&genre_counts[tk[k]]);
        tv[k]  = __ldg(&tok_table[tk[k] * EV + lane]);
    }

    // ---- phase 2: genre means (interleaved across the 2 tokens for MLP) ----
    float4 acc[BPW];
    #pragma unroll
    for (int k = 0; k < BPW; k++)
        acc[k] = make_float4(0.f, 0.f, 0.f, 0.f);

    #pragma unroll
    for (int k = 0; k < BPW; k++) {
        // Register-resident gid array (constant indices after unroll -> moves).
        int g[MAX_G];
        g[0] = ga[k].x; g[1] = ga[k].y; g[2] = ga[k].z; g[3] = ga[k].w;
        g[4] = gb[k].x; g[5] = gb[k].y; g[6] = gb[k].z; g[7] = gb[k].w;

        #pragma unroll
        for (int j = 0; j < MAX_G; j++) {
            if (j < cnt[k]) {   // predicated-off loads emit no L1 wavefront
                const float4 gv = __ldg(&genre_table[g[j] * EV + lane]);
                acc[k].x += gv.x; acc[k].y += gv.y;
                acc[k].z += gv.z; acc[k].w += gv.w;
            }
        }
    }

    // ---- phase 3: combine + store ----
    #pragma unroll
    for (int k = 0; k < BPW; k++) {
        const float inv = 1.0f / (float)cnt[k];
        float4 o;
        o.x = tv[k].x + acc[k].x * inv + pv.x;
        o.y = tv[k].y + acc[k].y * inv + pv.y;
        o.z = tv[k].z + acc[k].z * inv + pv.z;
        o.w = tv[k].w + acc[k].w * inv + pv.w;

        if (full || b0 + k < B)
            out[((b0 + k) * L + l) * EV + lane] = o;
    }
}

extern "C" void kernel_launch(void* const* d_in, const int* in_sizes, int n_in,
                              void* d_out, int out_size) {
    //   0: sequence        int32   [B*L] = 51200
    //   1: token_table     float32 [VOCAB*128]
    //   2: genre_table     float32 [(NG+1)*128]
    //   3: pos_table       float32 [MAX_LEN*128]
    //   4: token_genre_ids int32   [VOCAB*8]
    //   5: genre_counts    int32   [VOCAB]
    const int*    seq          = (const int*)   d_in[0];
    const float4* tok_table    = (const float4*)d_in[1];
    const float4* genre_table  = (const float4*)d_in[2];
    const float4* pos_table    = (const float4*)d_in[3];
    const int4*   token_gids   = (const int4*)  d_in[4];
    const int*    genre_counts = (const int*)   d_in[5];
    float4*       out          = (float4*)      d_out;

    const int n_tokens = in_sizes[0];          // 51200
    const int L        = in_sizes[3] / 128;    // 200
    const int B        = n_tokens / L;         // 256

    const int warps_needed = L * ((B + BPW - 1) / BPW);  // 200*128 = 25600
    const int threads      = 256;                        // 8 warps/block
    const int blocks       = (warps_needed + 7) / 8;     // 3200

    bert_embed_kernel<<<blocks, threads>>>(seq, tok_table, genre_table,
                                           pos_table, token_gids, genre_counts,
                                           out, L, B);
}

// round 16
// speedup vs baseline: 1.1552x; 1.1552x over previous
#include <cuda_runtime.h>
#include <cuda_bf16.h>

// BERT embedding fused gather — round 15: block-staged metadata.
// out[t,:] = token_table[seq[t]] + mean_{g<cnt} genre_table[gids[seq[t],g]] + pos_table[t % L]
//
// R14 post-mortem: occupancy-first failed (occ 50.8%, issue 46.6%, 17.2us).
// The binding constraint is the 3-deep dependent gather chain per warp
// (seq -> meta -> genre), ~750 cyc exposed with too little work to overlap.
//
// R15 design:
//  Phase A (block cooperative):
//    - 32 consecutive tokens per block; seq loaded as ONE coalesced wavefront
//    - all 32x8 genre ids gathered with one-gid-per-thread (256-way MLP)
//    - counts gathered by 32 threads
//    -> metadata lands in smem; per-warp chain shrinks to ONE L2 level
//  Phase B (warp work): each of 8 warps owns 4 consecutive tokens, processed
//    as 2 pairs with full load prefetch (tok rows, pos rows, genre rows).
//    pos rows consecutive, stores 16KB contiguous per block.
// smem 1.3 KB, regs ~45, __launch_bounds__(256,5).

#define EV      32   // 128 floats = 32 float4
#define MAX_G   8
#define TPB_TOK 32   // tokens per block (256 threads)

__global__ __launch_bounds__(256, 5) void bert_embed_kernel(
    const int*    __restrict__ seq,          // [B*L]
    const float4* __restrict__ tok_table,    // [VOCAB][32]
    const float4* __restrict__ genre_table,  // [NG][32]
    const float4* __restrict__ pos_table,    // [MAX_LEN][32]
    const int*    __restrict__ token_gids,   // [VOCAB][8] (int view)
    const int*    __restrict__ genre_counts, // [VOCAB]
    float4*       __restrict__ out,          // [B*L][32]
    int n_tokens, int L)
{
    __shared__ int s_tok[TPB_TOK];
    __shared__ int s_cnt[TPB_TOK];
    __shared__ int s_gid[TPB_TOK * MAX_G];

    const int tid = threadIdx.x;
    const int t0  = blockIdx.x * TPB_TOK;

    // ---- Phase A1: coalesced seq load (one 128B wavefront) ----
    if (tid < TPB_TOK) {
        const int t = t0 + tid;
        s_tok[tid] = (t < n_tokens) ? __ldg(&seq[t]) : 0;
    }
    __syncthreads();

    // ---- Phase A2: block-wide metadata gather, 256-way MLP ----
    {
        const int tok = s_tok[tid >> 3];                 // 8 threads per token
        s_gid[tid] = __ldg(&token_gids[tok * MAX_G + (tid & 7)]);
        if (tid < TPB_TOK)
            s_cnt[tid] = __ldg(&genre_counts[s_tok[tid]]);
    }
    __syncthreads();

    // ---- Phase B: each warp processes 4 consecutive tokens as 2 pairs ----
    const int lane = tid & 31;
    const int warp = tid >> 5;           // 0..7

    #pragma unroll
    for (int p = 0; p < 2; p++) {
        const int k0 = warp * 4 + p * 2;     // local token index (pair start)
        const int tA = t0 + k0;
        const int tB = t0 + k0 + 1;

        // metadata from smem (broadcast LDS, ~29 cyc — no L2 round trip)
        const int tokA = s_tok[k0],     tokB = s_tok[k0 + 1];
        const int cntA = s_cnt[k0],     cntB = s_cnt[k0 + 1];

        // issue all independent long-latency loads for the pair
        const float4 tvA = __ldg(&tok_table[tokA * EV + lane]);
        const float4 tvB = __ldg(&tok_table[tokB * EV + lane]);

        int lA = tA % L;
        int lB = tB % L;
        const float4 pvA = __ldg(&pos_table[lA * EV + lane]);
        const float4 pvB = __ldg(&pos_table[lB * EV + lane]);

        float4 accA = make_float4(0.f, 0.f, 0.f, 0.f);
        float4 accB = make_float4(0.f, 0.f, 0.f, 0.f);

        #pragma unroll
        for (int j = 0; j < MAX_G; j++) {
            if (j < cntA) {   // warp-uniform predicate: off => no L1 wavefront
                const float4 gv = __ldg(&genre_table[s_gid[k0 * MAX_G + j] * EV + lane]);
                accA.x += gv.x; accA.y += gv.y; accA.z += gv.z; accA.w += gv.w;
            }
            if (j < cntB) {
                const float4 gv = __ldg(&genre_table[s_gid[(k0 + 1) * MAX_G + j] * EV + lane]);
                accB.x += gv.x; accB.y += gv.y; accB.z += gv.z; accB.w += gv.w;
            }
        }

        const float invA = 1.0f / (float)cntA;
        const float invB = 1.0f / (float)cntB;

        float4 oA, oB;
        oA.x = tvA.x + accA.x * invA + pvA.x;
        oA.y = tvA.y + accA.y * invA + pvA.y;
        oA.z = tvA.z + accA.z * invA + pvA.z;
        oA.w = tvA.w + accA.w * invA + pvA.w;

        oB.x = tvB.x + accB.x * invB + pvB.x;
        oB.y = tvB.y + accB.y * invB + pvB.y;
        oB.z = tvB.z + accB.z * invB + pvB.z;
        oB.w = tvB.w + accB.w * invB + pvB.w;

        if (tA < n_tokens) out[tA * EV + lane] = oA;
        if (tB < n_tokens) out[tB * EV + lane] = oB;
    }
}

extern "C" void kernel_launch(void* const* d_in, const int* in_sizes, int n_in,
                              void* d_out, int out_size) {
    //   0: sequence        int32   [B*L] = 51200
    //   1: token_table     float32 [VOCAB*128]
    //   2: genre_table     float32 [(NG+1)*128]
    //   3: pos_table       float32 [MAX_LEN*128]
    //   4: token_genre_ids int32   [VOCAB*8]
    //   5: genre_counts    int32   [VOCAB]
    const int*    seq          = (const int*)   d_in[0];
    const float4* tok_table    = (const float4*)d_in[1];
    const float4* genre_table  = (const float4*)d_in[2];
    const float4* pos_table    = (const float4*)d_in[3];
    const int*    token_gids   = (const int*)   d_in[4];
    const int*    genre_counts = (const int*)   d_in[5];
    float4*       out          = (float4*)      d_out;

    const int n_tokens = in_sizes[0];          // 51200
    const int L        = in_sizes[3] / 128;    // 200

    const int threads = 256;
    const int blocks  = (n_tokens + TPB_TOK - 1) / TPB_TOK;   // 1600

    bert_embed_kernel<<<blocks, threads>>>(seq, tok_table, genre_table,
                                           pos_table, token_gids, genre_counts,
                                           out, n_tokens, L);
}